// round 3
// baseline (speedup 1.0000x reference)
#include <cuda_runtime.h>

#define N_NODES 8192
#define D 128
#define KNBR 8
#define LN_EPS 1e-5f
#define NEGBIG -1e30f

// ---------------- scratch (device globals: no allocation allowed) ----------
__device__ float g_buf0[N_NODES * D];
__device__ float g_buf1[N_NODES * D];
__device__ float g_buf2[N_NODES * D];
__device__ float g_dinv[N_NODES];
__device__ int   g_keptn[N_NODES * KNBR];
__device__ int   g_kcnt[N_NODES];

// ---------------- graph prep: dedup neighbors, degree^-1/2 -----------------
__global__ void prep_kernel(const int* __restrict__ neigh,
                            const int* __restrict__ nbrc) {
    int i = blockIdx.x * blockDim.x + threadIdx.x;
    if (i >= N_NODES) return;
    int cnt = nbrc[i];
    cnt = cnt > KNBR ? KNBR : (cnt < 0 ? 0 : cnt);
    int kept[KNBR];
    int kc = 0;
    for (int k = 0; k < cnt; ++k) {
        int nb = neigh[i * KNBR + k];
        if (nb == i) continue;          // merges with self-loop (diag set to 1)
        bool dup = false;
        for (int t = 0; t < kc; ++t) if (kept[t] == nb) dup = true;
        if (!dup) kept[kc++] = nb;      // A = min(A, 1): multi-edges count once
    }
    for (int t = 0; t < kc; ++t) g_keptn[i * KNBR + t] = kept[t];
    g_kcnt[i] = kc;
    g_dinv[i] = rsqrtf((float)(kc + 1));   // +1 for the self loop
}

// ---------------- fused GEMM: C = [A1|A2] @ W^T + b, epilogue variants -----
// W is row-major [128][wstride]; A2 may be null (K=128) or set (K=256).
// mode 0: plain   mode 1: relu   mode 2: LN(relu(C)+res)
#define TM 32
#define M_PLAIN 0
#define M_RELU  1
#define M_LN    2

__global__ __launch_bounds__(256)
void gemm_kernel(const float* __restrict__ A1, const float* __restrict__ A2,
                 const float* __restrict__ W, int wstride,
                 const float* __restrict__ bias,
                 const float* __restrict__ res,
                 const float* __restrict__ lng, const float* __restrict__ lnb,
                 float* __restrict__ out, int ostride, int ooff, int mode) {
    __shared__ float sA[TM][64];
    __shared__ float sW[64][132];   // sW[k][n], transposed; pad keeps f4 aligned

    const int tid = threadIdx.x;
    const int tx = tid & 31;        // col group: cols tx*4 .. tx*4+3
    const int ty = tid >> 5;        // row group (= warp id): rows ty*4 .. ty*4+3
    const int m0 = blockIdx.x * TM;

    float acc[4][4] = {};
    const int nseg = A2 ? 4 : 2;    // K in chunks of 64

    for (int seg = 0; seg < nseg; ++seg) {
        const float* A = (seg < 2) ? A1 : A2;
        const int akoff = (seg & 1) * 64;
        const int wkoff = seg * 64;
        __syncthreads();
        // stage A tile: 32 rows x 64 cols
        {
            int t = tid;
#pragma unroll
            for (int it = 0; it < 2; ++it, t += 256) {
                int r = t >> 4, c4 = (t & 15) << 2;
                *(float4*)&sA[r][c4] =
                    *(const float4*)&A[(m0 + r) * D + akoff + c4];
            }
        }
        // stage W chunk transposed: sW[k][n] = W[n][wkoff+k]
        {
            int t = tid;
#pragma unroll
            for (int it = 0; it < 8; ++it, t += 256) {
                int n = t >> 4, k4 = (t & 15) << 2;
                float4 w = *(const float4*)&W[n * wstride + wkoff + k4];
                sW[k4 + 0][n] = w.x;
                sW[k4 + 1][n] = w.y;
                sW[k4 + 2][n] = w.z;
                sW[k4 + 3][n] = w.w;
            }
        }
        __syncthreads();
#pragma unroll 8
        for (int k = 0; k < 64; ++k) {
            float4 w4 = *(const float4*)&sW[k][tx << 2];
            float a0 = sA[(ty << 2) + 0][k];
            float a1 = sA[(ty << 2) + 1][k];
            float a2 = sA[(ty << 2) + 2][k];
            float a3 = sA[(ty << 2) + 3][k];
            acc[0][0] += a0 * w4.x; acc[0][1] += a0 * w4.y;
            acc[0][2] += a0 * w4.z; acc[0][3] += a0 * w4.w;
            acc[1][0] += a1 * w4.x; acc[1][1] += a1 * w4.y;
            acc[1][2] += a1 * w4.z; acc[1][3] += a1 * w4.w;
            acc[2][0] += a2 * w4.x; acc[2][1] += a2 * w4.y;
            acc[2][2] += a2 * w4.z; acc[2][3] += a2 * w4.w;
            acc[3][0] += a3 * w4.x; acc[3][1] += a3 * w4.y;
            acc[3][2] += a3 * w4.z; acc[3][3] += a3 * w4.w;
        }
    }

    // ------------- epilogue -------------
    const int n0 = tx << 2;
    const int mb = m0 + (ty << 2);
    float bj[4] = { bias[n0], bias[n0 + 1], bias[n0 + 2], bias[n0 + 3] };

    if (mode == M_PLAIN) {
#pragma unroll
        for (int i = 0; i < 4; ++i)
#pragma unroll
            for (int j = 0; j < 4; ++j)
                out[(mb + i) * ostride + ooff + n0 + j] = acc[i][j] + bj[j];
    } else if (mode == M_RELU) {
#pragma unroll
        for (int i = 0; i < 4; ++i)
#pragma unroll
            for (int j = 0; j < 4; ++j)
                out[(mb + i) * ostride + ooff + n0 + j] =
                    fmaxf(acc[i][j] + bj[j], 0.f);
    } else {
        // LN(relu(C)+res): each warp (fixed ty) owns 4 complete rows
        float v[4][4];
#pragma unroll
        for (int i = 0; i < 4; ++i)
#pragma unroll
            for (int j = 0; j < 4; ++j)
                v[i][j] = fmaxf(acc[i][j] + bj[j], 0.f) +
                          res[(mb + i) * D + n0 + j];
        float gj[4] = { lng[n0], lng[n0 + 1], lng[n0 + 2], lng[n0 + 3] };
        float oj[4] = { lnb[n0], lnb[n0 + 1], lnb[n0 + 2], lnb[n0 + 3] };
#pragma unroll
        for (int i = 0; i < 4; ++i) {
            float s  = v[i][0] + v[i][1] + v[i][2] + v[i][3];
            float ss = v[i][0] * v[i][0] + v[i][1] * v[i][1] +
                       v[i][2] * v[i][2] + v[i][3] * v[i][3];
#pragma unroll
            for (int off = 16; off; off >>= 1) {
                s  += __shfl_xor_sync(0xffffffffu, s,  off);
                ss += __shfl_xor_sync(0xffffffffu, ss, off);
            }
            float mean = s * (1.0f / 128.0f);
            float var  = ss * (1.0f / 128.0f) - mean * mean;
            float rstd = rsqrtf(var + LN_EPS);
#pragma unroll
            for (int j = 0; j < 4; ++j)
                out[(mb + i) * ostride + ooff + n0 + j] =
                    (v[i][j] - mean) * rstd * gj[j] + oj[j];
        }
    }
}

// ---------------- GCN: h = LN(relu(Ah @ nxt) + res)  (warp per node) -------
__global__ __launch_bounds__(256)
void prop_ln_kernel(const float* __restrict__ nxt, const float* __restrict__ res,
                    const float* __restrict__ lng, const float* __restrict__ lnb,
                    float* __restrict__ out, int ostride, int ooff) {
    const int lane = threadIdx.x & 31;
    const int i = (blockIdx.x << 3) + (threadIdx.x >> 5);
    const float di = g_dinv[i];

    float acc[4];
    const float* self = nxt + i * D;
#pragma unroll
    for (int q = 0; q < 4; ++q) acc[q] = di * self[lane + 32 * q];

    const int kc = g_kcnt[i];
    const int* kn = &g_keptn[i * KNBR];
    for (int k = 0; k < kc; ++k) {
        int j = kn[k];
        float dj = g_dinv[j];
        const float* row = nxt + j * D;
#pragma unroll
        for (int q = 0; q < 4; ++q) acc[q] += dj * row[lane + 32 * q];
    }

    float v[4], s = 0.f, ss = 0.f;
    const float* rr = res + i * D;
#pragma unroll
    for (int q = 0; q < 4; ++q) {
        float p = fmaxf(di * acc[q], 0.f);
        v[q] = p + rr[lane + 32 * q];
        s += v[q];
        ss += v[q] * v[q];
    }
#pragma unroll
    for (int off = 16; off; off >>= 1) {
        s  += __shfl_xor_sync(0xffffffffu, s,  off);
        ss += __shfl_xor_sync(0xffffffffu, ss, off);
    }
    float mean = s * (1.0f / 128.0f);
    float rstd = rsqrtf(ss * (1.0f / 128.0f) - mean * mean + LN_EPS);
#pragma unroll
    for (int q = 0; q < 4; ++q) {
        int d = lane + 32 * q;
        out[i * ostride + ooff + d] = (v[q] - mean) * rstd * lng[d] + lnb[d];
    }
}

// ---------------- SAGE max-pool over valid neighbors (warp per node) -------
__global__ __launch_bounds__(256)
void pool_kernel(const float* __restrict__ src, const int* __restrict__ neigh,
                 const int* __restrict__ nbrc, float* __restrict__ out) {
    const int lane = threadIdx.x & 31;
    const int i = (blockIdx.x << 3) + (threadIdx.x >> 5);
    int cnt = nbrc[i];
    cnt = cnt > KNBR ? KNBR : (cnt < 0 ? 0 : cnt);
    if (cnt == 0) {
#pragma unroll
        for (int q = 0; q < 4; ++q) out[i * D + lane + 32 * q] = 0.f;
        return;
    }
    float m[4] = { NEGBIG, NEGBIG, NEGBIG, NEGBIG };
    for (int k = 0; k < cnt; ++k) {
        int j = neigh[i * KNBR + k];
        const float* row = src + j * D;
#pragma unroll
        for (int q = 0; q < 4; ++q) m[q] = fmaxf(m[q], row[lane + 32 * q]);
    }
#pragma unroll
    for (int q = 0; q < 4; ++q) out[i * D + lane + 32 * q] = m[q];
}

// ---------------- driver ----------------------------------------------------
extern "C" void kernel_launch(void* const* d_in, const int* in_sizes, int n_in,
                              void* d_out, int out_size) {
    const float* x    = (const float*)d_in[0];
    const int*   nei  = (const int*)  d_in[1];
    const int*   nbc  = (const int*)  d_in[2];
    const float* gW   = (const float*)d_in[3];   // [3,128,128]
    const float* gb   = (const float*)d_in[4];   // [3,128]
    const float* glg  = (const float*)d_in[5];
    const float* glb  = (const float*)d_in[6];
    const float* pW   = (const float*)d_in[7];   // [128,128]
    const float* pb   = (const float*)d_in[8];
    const float* mW   = (const float*)d_in[9];   // [3,128,256]
    const float* mb   = (const float*)d_in[10];  // [3,128]
    const float* slg  = (const float*)d_in[11];  // [2,128]
    const float* slb  = (const float*)d_in[12];
    float* out = (float*)d_out;

    float *b0, *b1, *b2;
    cudaGetSymbolAddress((void**)&b0, g_buf0);
    cudaGetSymbolAddress((void**)&b1, g_buf1);
    cudaGetSymbolAddress((void**)&b2, g_buf2);

    const int GB = N_NODES / TM;       // 256 gemm blocks
    const int WB = N_NODES / 8;        // 1024 warp-per-node blocks

    prep_kernel<<<N_NODES / 256, 256>>>(nei, nbc);

    // ---- GCN branch ----
    // layer 0: nxt0 = x@W0^T+b0 ; h = LN(relu(Ah@nxt0) + nxt0)
    gemm_kernel<<<GB, 256>>>(x, nullptr, gW, D, gb,
                             nullptr, nullptr, nullptr, b0, D, 0, M_PLAIN);
    prop_ln_kernel<<<WB, 256>>>(b0, b0, glg, glb, b1, D, 0);
    // layer 1
    gemm_kernel<<<GB, 256>>>(b1, nullptr, gW + D * D, D, gb + D,
                             nullptr, nullptr, nullptr, b0, D, 0, M_PLAIN);
    prop_ln_kernel<<<WB, 256>>>(b0, b1, glg + D, glb + D, b1, D, 0);
    // layer 2 -> out[:, 0:128]
    gemm_kernel<<<GB, 256>>>(b1, nullptr, gW + 2 * D * D, D, gb + 2 * D,
                             nullptr, nullptr, nullptr, b0, D, 0, M_PLAIN);
    prop_ln_kernel<<<WB, 256>>>(b0, b1, glg + 2 * D, glb + 2 * D, out, 2 * D, 0);

    // ---- SAGE branch ----
    // ne1 = relu(x@poolW^T+pb)
    gemm_kernel<<<GB, 256>>>(x, nullptr, pW, D, pb,
                             nullptr, nullptr, nullptr, b0, D, 0, M_RELU);
    pool_kernel<<<WB, 256>>>(b0, nei, nbc, b1);
    // s = relu([x | pool] @ W0^T + b0)
    gemm_kernel<<<GB, 256>>>(x, b1, mW, 2 * D, mb,
                             nullptr, nullptr, nullptr, b2, D, 0, M_RELU);
    // layer 1: s = LN(relu([s | pool(s)]@W1^T+b1) + s)
    pool_kernel<<<WB, 256>>>(b2, nei, nbc, b1);
    gemm_kernel<<<GB, 256>>>(b2, b1, mW + D * 2 * D, 2 * D, mb + D,
                             b2, slg, slb, b2, D, 0, M_LN);
    // layer 2 -> out[:, 128:256]
    pool_kernel<<<WB, 256>>>(b2, nei, nbc, b1);
    gemm_kernel<<<GB, 256>>>(b2, b1, mW + 2 * D * 2 * D, 2 * D, mb + 2 * D,
                             b2, slg + D, slb + D, out, 2 * D, D, M_LN);
}

// round 6
// speedup vs baseline: 1.5160x; 1.5160x over previous
#include <cuda_runtime.h>
#include <cuda_bf16.h>
#include <cstdint>

#define N_NODES 8192
#define D 128
#define KNBR 8
#define LN_EPS 1e-5f
#define NEGBIG -1e30f

#define M_PLAIN 0
#define M_RELU  1
#define M_LN    2

#define MTILE 64
// SMEM layout (bytes): Ah[64x128 bf16]=16K, Al=16K, Wh[128x128 bf16]=32K, Wl=32K
#define OFF_AH 0
#define OFF_AL 16384
#define OFF_WH 32768
#define OFF_WL 65536
#define SMEM_TOTAL 98304
#define WTILE_BYTES 32768   // one pre-split W chunk [128 n][128 k] bf16

// ---------------- scratch (device globals: no allocation allowed) ----------
__device__ float g_buf0[N_NODES * D];
__device__ float g_buf1[N_NODES * D];
__device__ float g_buf2[N_NODES * D];
__device__ float g_dinv[N_NODES];
__device__ int   g_keptn[N_NODES * KNBR];
__device__ int   g_kcnt[N_NODES];
// pre-split, pre-swizzled weights: 10 chunks of [128 rows x 128 cols] bf16
__device__ __align__(16) unsigned char g_wh[10 * WTILE_BYTES];
__device__ __align__(16) unsigned char g_wl[10 * WTILE_BYTES];

// ---------------- helpers ---------------------------------------------------
__device__ __forceinline__ uint32_t smem_u32(const void* p) {
    uint32_t a;
    asm("{ .reg .u64 t; cvta.to.shared.u64 t, %1; cvt.u32.u64 %0, t; }"
        : "=r"(a) : "l"(p));
    return a;
}
__device__ __forceinline__ void ldsm4(uint32_t addr, uint32_t* r) {
    asm volatile("ldmatrix.sync.aligned.m8n8.x4.shared.b16 {%0,%1,%2,%3}, [%4];"
                 : "=r"(r[0]), "=r"(r[1]), "=r"(r[2]), "=r"(r[3]) : "r"(addr));
}
__device__ __forceinline__ void mma_bf16(float* d, const uint32_t* a,
                                         uint32_t b0, uint32_t b1) {
    asm volatile(
        "mma.sync.aligned.m16n8k16.row.col.f32.bf16.bf16.f32 "
        "{%0,%1,%2,%3}, {%4,%5,%6,%7}, {%8,%9}, {%0,%1,%2,%3};"
        : "+f"(d[0]), "+f"(d[1]), "+f"(d[2]), "+f"(d[3])
        : "r"(a[0]), "r"(a[1]), "r"(a[2]), "r"(a[3]), "r"(b0), "r"(b1));
}
static __device__ __forceinline__ uint32_t bf2u(__nv_bfloat162 v) {
    return *reinterpret_cast<uint32_t*>(&v);
}
// pack 8 consecutive floats -> hi uint4 / lo uint4 (bf16 pairs, low k = low bits)
__device__ __forceinline__ void split8(const float* f, uint4& hi, uint4& lo) {
    __nv_bfloat16 h[8];
    float l[8];
#pragma unroll
    for (int e = 0; e < 8; ++e) {
        h[e] = __float2bfloat16(f[e]);
        l[e] = f[e] - __bfloat162float(h[e]);
    }
    hi.x = bf2u(__halves2bfloat162(h[0], h[1]));
    hi.y = bf2u(__halves2bfloat162(h[2], h[3]));
    hi.z = bf2u(__halves2bfloat162(h[4], h[5]));
    hi.w = bf2u(__halves2bfloat162(h[6], h[7]));
    lo.x = bf2u(__floats2bfloat162_rn(l[0], l[1]));
    lo.y = bf2u(__floats2bfloat162_rn(l[2], l[3]));
    lo.z = bf2u(__floats2bfloat162_rn(l[4], l[5]));
    lo.w = bf2u(__floats2bfloat162_rn(l[6], l[7]));
}

// ---------------- graph prep: dedup neighbors, degree^-1/2 -----------------
__global__ void prep_kernel(const int* __restrict__ neigh,
                            const int* __restrict__ nbrc) {
    int i = blockIdx.x * blockDim.x + threadIdx.x;
    if (i >= N_NODES) return;
    int cnt = nbrc[i];
    cnt = cnt > KNBR ? KNBR : (cnt < 0 ? 0 : cnt);
    int kept[KNBR];
    int kc = 0;
    for (int k = 0; k < cnt; ++k) {
        int nb = neigh[i * KNBR + k];
        if (nb == i) continue;
        bool dup = false;
        for (int t = 0; t < kc; ++t) if (kept[t] == nb) dup = true;
        if (!dup) kept[kc++] = nb;
    }
    for (int t = 0; t < kc; ++t) g_keptn[i * KNBR + t] = kept[t];
    g_kcnt[i] = kc;
    g_dinv[i] = rsqrtf((float)(kc + 1));
}

// ---------------- weight prep: bf16 hi/lo split + XOR swizzle --------------
// 10 chunks of [128 n-rows][128 k-cols]: 0-2 gcn, 3 pool, 4-9 merge (2/layer)
// layout: row stride 256B, 16B chunk index XORed with (row & 7)
__global__ void prep_w_kernel(const float* __restrict__ gW,
                              const float* __restrict__ pW,
                              const float* __restrict__ mW) {
    int c = blockIdx.x, tid = threadIdx.x;
    const float* src;
    int stride, coloff;
    if (c < 3)       { src = gW + c * 16384; stride = 128; coloff = 0; }
    else if (c == 3) { src = pW;             stride = 128; coloff = 0; }
    else { int l = (c - 4) >> 1, h = (c - 4) & 1;
           src = mW + l * 32768; stride = 256; coloff = h * 128; }
    unsigned char* wh = g_wh + c * WTILE_BYTES;
    unsigned char* wl = g_wl + c * WTILE_BYTES;
    for (int i = tid; i < 2048; i += 256) {       // 16B chunks
        int n = i >> 4, ch = i & 15;
        float f[8];
#pragma unroll
        for (int e = 0; e < 8; ++e) f[e] = src[n * stride + coloff + ch * 8 + e];
        uint4 hi, lo;
        split8(f, hi, lo);
        uint32_t off = (uint32_t)n * 256 + ((uint32_t)(ch ^ (n & 7)) << 4);
        *(uint4*)(wh + off) = hi;
        *(uint4*)(wl + off) = lo;
    }
}

// ---------------- HMMA GEMM: out = [A1|A2] @ W^T + b, epilogues ------------
// hi/lo split: D = Ah@Wh + Ah@Wl + Al@Wh (fp32 accum in fragments)
__global__ __launch_bounds__(256, 2)
void mma_gemm_kernel(const float* __restrict__ A1, const float* __restrict__ A2,
                     int wchunk,
                     const float* __restrict__ bias, const float* __restrict__ res,
                     const float* __restrict__ lng, const float* __restrict__ lnb,
                     float* __restrict__ out, int ostride, int ooff,
                     int mode, int nchunks) {
    extern __shared__ __align__(256) char smem_raw[];
    const uint32_t sbase = smem_u32(smem_raw);

    const int tid = threadIdx.x, wid = tid >> 5, lane = tid & 31;
    const int wm = wid & 1;          // row half: rows wm*32..+31
    const int wn = wid >> 1;         // col quarter: cols wn*32..+31
    const int m0 = blockIdx.x * MTILE;

    float acc[2][4][4];              // [i mtile][j ntile][reg]
#pragma unroll
    for (int i = 0; i < 2; ++i)
#pragma unroll
        for (int j = 0; j < 4; ++j)
#pragma unroll
            for (int r = 0; r < 4; ++r) acc[i][j][r] = 0.f;

    // per-lane ldmatrix row indices (row = lane%16 within 16-row group)
    const int lrow = lane & 15, lhalf = lane >> 4;
    const int rowA0 = wm * 32 + lrow, rowA1 = rowA0 + 16;
    const int rowB0 = wn * 32 + lrow, rowB1 = rowB0 + 16;

    for (int c = 0; c < nchunks; ++c) {
        if (c) __syncthreads();
        const float* Asrc = (c == 0) ? A1 : A2;
        // stage A: 64 rows x 16 chunks -> bf16 hi/lo, swizzled
        for (int i = tid; i < 1024; i += 256) {
            int r = i >> 4, ch = i & 15;
            float f[8];
            float4 f0 = *(const float4*)&Asrc[(m0 + r) * D + ch * 8];
            float4 f1 = *(const float4*)&Asrc[(m0 + r) * D + ch * 8 + 4];
            f[0] = f0.x; f[1] = f0.y; f[2] = f0.z; f[3] = f0.w;
            f[4] = f1.x; f[5] = f1.y; f[6] = f1.z; f[7] = f1.w;
            uint4 hi, lo;
            split8(f, hi, lo);
            uint32_t off = (uint32_t)r * 256 + ((uint32_t)(ch ^ (r & 7)) << 4);
            *(uint4*)(smem_raw + OFF_AH + off) = hi;
            *(uint4*)(smem_raw + OFF_AL + off) = lo;
        }
        // stage W: pure copy of pre-swizzled chunk
        {
            const uint4* wh4 = (const uint4*)(g_wh + (wchunk + c) * WTILE_BYTES);
            const uint4* wl4 = (const uint4*)(g_wl + (wchunk + c) * WTILE_BYTES);
            uint4* dh = (uint4*)(smem_raw + OFF_WH);
            uint4* dl = (uint4*)(smem_raw + OFF_WL);
            for (int i = tid; i < 2048; i += 256) { dh[i] = wh4[i]; dl[i] = wl4[i]; }
        }
        __syncthreads();

#pragma unroll
        for (int pass = 0; pass < 3; ++pass) {
            const uint32_t aB = sbase + (pass < 2 ? OFF_AH : OFF_AL);
            const uint32_t wB = sbase + (pass == 1 ? OFF_WL : OFF_WH);
#pragma unroll
            for (int ks = 0; ks < 8; ++ks) {
                const int ch = ks * 2 + lhalf;
                uint32_t a0[4], a1[4], b0[4], b1[4];
                ldsm4(aB + rowA0 * 256 + ((ch ^ (rowA0 & 7)) << 4), a0);
                ldsm4(aB + rowA1 * 256 + ((ch ^ (rowA1 & 7)) << 4), a1);
                ldsm4(wB + rowB0 * 256 + ((ch ^ (rowB0 & 7)) << 4), b0);
                ldsm4(wB + rowB1 * 256 + ((ch ^ (rowB1 & 7)) << 4), b1);
                // x4 on [16n x 16k]: r0=n0-7/k0-7, r1=n8-15/k0-7,
                //                    r2=n0-7/k8-15, r3=n8-15/k8-15
                mma_bf16(acc[0][0], a0, b0[0], b0[2]);
                mma_bf16(acc[0][1], a0, b0[1], b0[3]);
                mma_bf16(acc[0][2], a0, b1[0], b1[2]);
                mma_bf16(acc[0][3], a0, b1[1], b1[3]);
                mma_bf16(acc[1][0], a1, b0[0], b0[2]);
                mma_bf16(acc[1][1], a1, b0[1], b0[3]);
                mma_bf16(acc[1][2], a1, b1[0], b1[2]);
                mma_bf16(acc[1][3], a1, b1[1], b1[3]);
            }
        }
    }

    // ---- epilogue ----------------------------------------------------------
    // c-frag: thread t: rows (t/4, t/4+8), cols 2*(t%4), +1 within 16x8 tile
    const int frow = lane >> 2, fcol = 2 * (lane & 3);

    if (mode != M_LN) {
#pragma unroll
        for (int i = 0; i < 2; ++i)
#pragma unroll
            for (int j = 0; j < 4; ++j) {
                int ncol = wn * 32 + j * 8 + fcol;
                float2 bj = *(const float2*)&bias[ncol];
                int m = m0 + wm * 32 + i * 16 + frow;
                float2 v0 = make_float2(acc[i][j][0] + bj.x, acc[i][j][1] + bj.y);
                float2 v1 = make_float2(acc[i][j][2] + bj.x, acc[i][j][3] + bj.y);
                if (mode == M_RELU) {
                    v0.x = fmaxf(v0.x, 0.f); v0.y = fmaxf(v0.y, 0.f);
                    v1.x = fmaxf(v1.x, 0.f); v1.y = fmaxf(v1.y, 0.f);
                }
                *(float2*)&out[m * ostride + ooff + ncol] = v0;
                *(float2*)&out[(m + 8) * ostride + ooff + ncol] = v1;
            }
        return;
    }

    // LN: relu(C+b) -> SMEM, then per-row LayerNorm with residual
    float* sC = (float*)smem_raw;             // [64][132]
    __syncthreads();                          // all warps done reading A/W smem
#pragma unroll
    for (int i = 0; i < 2; ++i)
#pragma unroll
        for (int j = 0; j < 4; ++j) {
            int ncol = wn * 32 + j * 8 + fcol;
            float2 bj = *(const float2*)&bias[ncol];
            int r = wm * 32 + i * 16 + frow;
            sC[r * 132 + ncol]       = fmaxf(acc[i][j][0] + bj.x, 0.f);
            sC[r * 132 + ncol + 1]   = fmaxf(acc[i][j][1] + bj.y, 0.f);
            sC[(r + 8) * 132 + ncol]     = fmaxf(acc[i][j][2] + bj.x, 0.f);
            sC[(r + 8) * 132 + ncol + 1] = fmaxf(acc[i][j][3] + bj.y, 0.f);
        }
    __syncthreads();

    {
        const int row = tid >> 2, q = tid & 3;     // 4 threads per row
        const int m = m0 + row;
        float v[32];
        float s = 0.f, ss = 0.f;
#pragma unroll
        for (int t = 0; t < 8; ++t) {
            int col = q * 32 + t * 4;
            float4 cv = *(float4*)&sC[row * 132 + col];
            float4 rv = *(const float4*)&res[m * D + col];
            v[4 * t + 0] = cv.x + rv.x; v[4 * t + 1] = cv.y + rv.y;
            v[4 * t + 2] = cv.z + rv.z; v[4 * t + 3] = cv.w + rv.w;
            s  += v[4 * t] + v[4 * t + 1] + v[4 * t + 2] + v[4 * t + 3];
            ss += v[4 * t] * v[4 * t] + v[4 * t + 1] * v[4 * t + 1] +
                  v[4 * t + 2] * v[4 * t + 2] + v[4 * t + 3] * v[4 * t + 3];
        }
#pragma unroll
        for (int off = 1; off < 4; off <<= 1) {
            s  += __shfl_xor_sync(0xffffffffu, s,  off);
            ss += __shfl_xor_sync(0xffffffffu, ss, off);
        }
        float mean = s * (1.0f / 128.0f);
        float rstd = rsqrtf(ss * (1.0f / 128.0f) - mean * mean + LN_EPS);
#pragma unroll
        for (int t = 0; t < 8; ++t) {
            int col = q * 32 + t * 4;
            float4 gj = *(const float4*)&lng[col];
            float4 oj = *(const float4*)&lnb[col];
            float4 o;
            o.x = (v[4 * t + 0] - mean) * rstd * gj.x + oj.x;
            o.y = (v[4 * t + 1] - mean) * rstd * gj.y + oj.y;
            o.z = (v[4 * t + 2] - mean) * rstd * gj.z + oj.z;
            o.w = (v[4 * t + 3] - mean) * rstd * gj.w + oj.w;
            *(float4*)&out[m * ostride + ooff + col] = o;
        }
    }
}

// ---------------- GCN: h = LN(relu(Ah @ nxt) + res)  (warp/node, float4) ---
__global__ __launch_bounds__(256)
void prop_ln_kernel(const float* __restrict__ nxt, const float* __restrict__ res,
                    const float* __restrict__ lng, const float* __restrict__ lnb,
                    float* __restrict__ out, int ostride, int ooff) {
    const int lane = threadIdx.x & 31;
    const int i = (blockIdx.x << 3) + (threadIdx.x >> 5);
    const float di = g_dinv[i];

    float4 t = ((const float4*)(nxt + i * D))[lane];
    float4 acc = make_float4(di * t.x, di * t.y, di * t.z, di * t.w);

    const int kc = g_kcnt[i];
    const int* kn = &g_keptn[i * KNBR];
    for (int k = 0; k < kc; ++k) {
        int j = kn[k];
        float dj = g_dinv[j];
        float4 r = ((const float4*)(nxt + j * D))[lane];
        acc.x += dj * r.x; acc.y += dj * r.y;
        acc.z += dj * r.z; acc.w += dj * r.w;
    }

    float4 rr = ((const float4*)(res + i * D))[lane];
    float4 v;
    v.x = fmaxf(di * acc.x, 0.f) + rr.x;
    v.y = fmaxf(di * acc.y, 0.f) + rr.y;
    v.z = fmaxf(di * acc.z, 0.f) + rr.z;
    v.w = fmaxf(di * acc.w, 0.f) + rr.w;
    float s  = v.x + v.y + v.z + v.w;
    float ss = v.x * v.x + v.y * v.y + v.z * v.z + v.w * v.w;
#pragma unroll
    for (int off = 16; off; off >>= 1) {
        s  += __shfl_xor_sync(0xffffffffu, s,  off);
        ss += __shfl_xor_sync(0xffffffffu, ss, off);
    }
    float mean = s * (1.0f / 128.0f);
    float rstd = rsqrtf(ss * (1.0f / 128.0f) - mean * mean + LN_EPS);
    float4 gj = ((const float4*)lng)[lane];
    float4 oj = ((const float4*)lnb)[lane];
    float4 o;
    o.x = (v.x - mean) * rstd * gj.x + oj.x;
    o.y = (v.y - mean) * rstd * gj.y + oj.y;
    o.z = (v.z - mean) * rstd * gj.z + oj.z;
    o.w = (v.w - mean) * rstd * gj.w + oj.w;
    *(float4*)&out[i * ostride + ooff + 4 * lane] = o;
}

// ---------------- SAGE max-pool (warp/node, float4) ------------------------
__global__ __launch_bounds__(256)
void pool_kernel(const float* __restrict__ src, const int* __restrict__ neigh,
                 const int* __restrict__ nbrc, float* __restrict__ out) {
    const int lane = threadIdx.x & 31;
    const int i = (blockIdx.x << 3) + (threadIdx.x >> 5);
    int cnt = nbrc[i];
    cnt = cnt > KNBR ? KNBR : (cnt < 0 ? 0 : cnt);
    if (cnt == 0) {
        *(float4*)&out[i * D + 4 * lane] = make_float4(0.f, 0.f, 0.f, 0.f);
        return;
    }
    float4 m = make_float4(NEGBIG, NEGBIG, NEGBIG, NEGBIG);
    for (int k = 0; k < cnt; ++k) {
        int j = neigh[i * KNBR + k];
        float4 r = ((const float4*)(src + j * D))[lane];
        m.x = fmaxf(m.x, r.x); m.y = fmaxf(m.y, r.y);
        m.z = fmaxf(m.z, r.z); m.w = fmaxf(m.w, r.w);
    }
    *(float4*)&out[i * D + 4 * lane] = m;
}

// ---------------- driver ----------------------------------------------------
extern "C" void kernel_launch(void* const* d_in, const int* in_sizes, int n_in,
                              void* d_out, int out_size) {
    const float* x   = (const float*)d_in[0];
    const int*   nei = (const int*)  d_in[1];
    const int*   nbc = (const int*)  d_in[2];
    const float* gW  = (const float*)d_in[3];
    const float* gb  = (const float*)d_in[4];
    const float* glg = (const float*)d_in[5];
    const float* glb = (const float*)d_in[6];
    const float* pW  = (const float*)d_in[7];
    const float* pb  = (const float*)d_in[8];
    const float* mW  = (const float*)d_in[9];
    const float* mb  = (const float*)d_in[10];
    const float* slg = (const float*)d_in[11];
    const float* slb = (const float*)d_in[12];
    float* out = (float*)d_out;

    float *b0, *b1, *b2;
    cudaGetSymbolAddress((void**)&b0, g_buf0);
    cudaGetSymbolAddress((void**)&b1, g_buf1);
    cudaGetSymbolAddress((void**)&b2, g_buf2);

    cudaFuncSetAttribute(mma_gemm_kernel,
                         cudaFuncAttributeMaxDynamicSharedMemorySize, SMEM_TOTAL);

    const int GB = N_NODES / MTILE;    // 128 gemm tiles
    const int WB = N_NODES / 8;        // 1024 warp-per-node blocks

    prep_kernel<<<N_NODES / 256, 256>>>(nei, nbc);
    prep_w_kernel<<<10, 256>>>(gW, pW, mW);

    // ---- GCN branch ----
    mma_gemm_kernel<<<GB, 256, SMEM_TOTAL>>>(x, nullptr, 0, gb,
        nullptr, nullptr, nullptr, b0, D, 0, M_PLAIN, 1);
    prop_ln_kernel<<<WB, 256>>>(b0, b0, glg, glb, b1, D, 0);
    mma_gemm_kernel<<<GB, 256, SMEM_TOTAL>>>(b1, nullptr, 1, gb + D,
        nullptr, nullptr, nullptr, b0, D, 0, M_PLAIN, 1);
    prop_ln_kernel<<<WB, 256>>>(b0, b1, glg + D, glb + D, b1, D, 0);
    mma_gemm_kernel<<<GB, 256, SMEM_TOTAL>>>(b1, nullptr, 2, gb + 2 * D,
        nullptr, nullptr, nullptr, b0, D, 0, M_PLAIN, 1);
    prop_ln_kernel<<<WB, 256>>>(b0, b1, glg + 2 * D, glb + 2 * D, out, 2 * D, 0);

    // ---- SAGE branch ----
    mma_gemm_kernel<<<GB, 256, SMEM_TOTAL>>>(x, nullptr, 3, pb,
        nullptr, nullptr, nullptr, b0, D, 0, M_RELU, 1);
    pool_kernel<<<WB, 256>>>(b0, nei, nbc, b1);
    mma_gemm_kernel<<<GB, 256, SMEM_TOTAL>>>(x, b1, 4, mb,
        nullptr, nullptr, nullptr, b2, D, 0, M_RELU, 2);
    pool_kernel<<<WB, 256>>>(b2, nei, nbc, b1);
    mma_gemm_kernel<<<GB, 256, SMEM_TOTAL>>>(b2, b1, 6, mb + D,
        b2, slg, slb, b2, D, 0, M_LN, 2);
    pool_kernel<<<WB, 256>>>(b2, nei, nbc, b1);
    mma_gemm_kernel<<<GB, 256, SMEM_TOTAL>>>(b2, b1, 8, mb + 2 * D,
        b2, slg + D, slb + D, out, 2 * D, D, M_LN, 2);
}